// round 1
// baseline (speedup 1.0000x reference)
#include <cuda_runtime.h>

// IVPLoss: 8-step Euler trajectories of bilinear-sampled vector fields,
// MSE between pred and true trajectories (incl. identity step 0).
//
// Strategy:
//  1) repack_kernel: planar (B,2,H,W) float -> channel-interleaved float2
//     with one padded column (duplicate of col W-1) so x0+1 is always valid.
//     Also zeroes the double accumulator (graph-capture safe: same stream).
//  2) traj_kernel: one thread per (b,y,x); integrates BOTH trajectories in
//     registers, accumulates squared coordinate diffs, block-reduces,
//     atomicAdd(double) into g_acc.
//  3) finalize_kernel: writes mean to d_out.

#define Bv 8
#define Hv 768
#define Wv 768
#define WPAD 769
#define NSTEPS 8
#define DXC 0.5f

#define PLANE (Hv * Wv)            // 589824
#define PK_PLANE (Hv * WPAD)       // 590592
#define PK_TOTAL (Bv * PK_PLANE)   // 4724736

__device__ float2 g_pred[PK_TOTAL];
__device__ float2 g_true[PK_TOTAL];
__device__ double g_acc;

__global__ void repack_kernel(const float* __restrict__ pred,
                              const float* __restrict__ tru) {
    int idx = blockIdx.x * blockDim.x + threadIdx.x;
    if (idx == 0) g_acc = 0.0;
    if (idx >= PK_TOTAL) return;
    int x = idx % WPAD;
    int rest = idx / WPAD;
    int y = rest % Hv;
    int b = rest / Hv;
    int xs = min(x, Wv - 1);                       // padded col duplicates last col
    int src = b * 2 * PLANE + y * Wv + xs;          // channel 0
    g_pred[idx] = make_float2(__ldg(pred + src), __ldg(pred + src + PLANE));
    g_true[idx] = make_float2(__ldg(tru  + src), __ldg(tru  + src + PLANE));
}

__device__ __forceinline__ float2 bsample(const float2* __restrict__ P,
                                          float x, float y) {
    // clip to [0, W-1] / [0, H-1] (matches jnp.clip)
    x = fminf(fmaxf(x, 0.0f), (float)(Wv - 1));
    y = fminf(fmaxf(y, 0.0f), (float)(Hv - 1));
    float xf = floorf(x);
    float yf = floorf(y);
    int xi = (int)xf;
    int yi = (int)yf;
    int yi1 = min(yi + 1, Hv - 1);
    float wx = x - xf;
    float wy = y - yf;
    const float2* r0 = P + yi  * WPAD + xi;
    const float2* r1 = P + yi1 * WPAD + xi;
    float2 v00 = __ldg(r0);
    float2 v01 = __ldg(r0 + 1);   // padded column makes xi+1 always in-bounds
    float2 v10 = __ldg(r1);
    float2 v11 = __ldg(r1 + 1);
    float tx = fmaf(wx, v01.x - v00.x, v00.x);
    float ty = fmaf(wx, v01.y - v00.y, v00.y);
    float bx = fmaf(wx, v11.x - v10.x, v10.x);
    float by = fmaf(wx, v11.y - v10.y, v10.y);
    return make_float2(fmaf(wy, bx - tx, tx), fmaf(wy, by - ty, ty));
}

__global__ __launch_bounds__(256) void traj_kernel() {
    int x = blockIdx.x * blockDim.x + threadIdx.x;  // 0..767
    int y = blockIdx.y;
    int b = blockIdx.z;
    const float2* __restrict__ Pp = g_pred + b * PK_PLANE;
    const float2* __restrict__ Pt = g_true + b * PK_PLANE;

    float pxp = (float)x, pyp = (float)y;   // pred trajectory
    float pxt = (float)x, pyt = (float)y;   // true trajectory
    float acc = 0.0f;

    #pragma unroll
    for (int s = 0; s < NSTEPS; s++) {
        float2 vp = bsample(Pp, pxp, pyp);
        float2 vt = bsample(Pt, pxt, pyt);
        pxp = fmaf(DXC, vp.x, pxp);
        pyp = fmaf(DXC, vp.y, pyp);
        pxt = fmaf(DXC, vt.x, pxt);
        pyt = fmaf(DXC, vt.y, pyt);
        float dx = pxt - pxp;
        float dy = pyt - pyp;
        acc = fmaf(dx, dx, acc);
        acc = fmaf(dy, dy, acc);
    }

    // block reduction: warp shuffle -> shared -> warp0 -> atomicAdd(double)
    float v = acc;
    #pragma unroll
    for (int o = 16; o > 0; o >>= 1)
        v += __shfl_down_sync(0xffffffffu, v, o);

    __shared__ float sred[8];
    int lane = threadIdx.x & 31;
    int wid  = threadIdx.x >> 5;
    if (lane == 0) sred[wid] = v;
    __syncthreads();
    if (wid == 0) {
        v = (lane < 8) ? sred[lane] : 0.0f;
        #pragma unroll
        for (int o = 4; o > 0; o >>= 1)
            v += __shfl_down_sync(0xffffffffu, v, o);
        if (lane == 0) atomicAdd(&g_acc, (double)v);
    }
}

__global__ void finalize_kernel(float* __restrict__ out) {
    const double cnt = (double)(NSTEPS + 1) * Bv * 2 * Hv * Wv;  // 84934656
    *out = (float)(g_acc / cnt);
}

extern "C" void kernel_launch(void* const* d_in, const int* in_sizes, int n_in,
                              void* d_out, int out_size) {
    const float* vf_pred = (const float*)d_in[0];
    const float* vf_true = (const float*)d_in[1];
    float* out = (float*)d_out;

    int rp_blocks = (PK_TOTAL + 255) / 256;
    repack_kernel<<<rp_blocks, 256>>>(vf_pred, vf_true);

    dim3 grid(Wv / 256, Hv, Bv);
    traj_kernel<<<grid, 256>>>();

    finalize_kernel<<<1, 1>>>(out);
}

// round 2
// speedup vs baseline: 1.5482x; 1.5482x over previous
#include <cuda_runtime.h>
#include <cuda_fp16.h>

// IVPLoss: 8-step Euler trajectories of bilinear-sampled vector fields,
// MSE between pred and true trajectories (incl. identity step 0).
//
// R2: fields repacked to fp16, channel-interleaved, DUPLICATED-PAIR layout:
//   elem(y,x) = { half2(c0[x],c1[x]), half2(c0[x+1],c1[x+1]) }  (8 bytes)
// -> one bilinear sample = 2 coalesced LDG.64 (one per row) + HFMA2 lerps.
// Positions/accumulation remain fp32/fp64; fp16 only stores field values.

#define Bv 8
#define Hv 768
#define Wv 768
#define WPAD 769
#define NSTEPS 8
#define DXC 0.5f

#define PLANE (Hv * Wv)            // 589824
#define PK_PLANE (Hv * WPAD)       // 590592
#define PK_TOTAL (Bv * PK_PLANE)   // 4724736

// each element: .x = half2(c0[x], c1[x]), .y = half2(c0[x+1], c1[x+1])
__device__ uint2 g_pred[PK_TOTAL];
__device__ uint2 g_true[PK_TOTAL];
__device__ double g_acc;

__device__ __forceinline__ uint2 pack_pair(const float* __restrict__ f,
                                           int base, int x) {
    int x1 = min(x + 1, Wv - 1);
    __half2 p0 = __floats2half2_rn(__ldg(f + base + x),
                                   __ldg(f + base + PLANE + x));
    __half2 p1 = __floats2half2_rn(__ldg(f + base + x1),
                                   __ldg(f + base + PLANE + x1));
    uint2 r;
    r.x = *reinterpret_cast<unsigned int*>(&p0);
    r.y = *reinterpret_cast<unsigned int*>(&p1);
    return r;
}

__global__ void repack_kernel(const float* __restrict__ pred,
                              const float* __restrict__ tru) {
    int idx = blockIdx.x * blockDim.x + threadIdx.x;
    if (idx == 0) g_acc = 0.0;
    if (idx >= PK_TOTAL) return;
    int x = idx % WPAD;
    int rest = idx / WPAD;
    int y = rest % Hv;
    int b = rest / Hv;
    int xs = min(x, Wv - 1);                 // padded col duplicates last col
    int base = b * 2 * PLANE + y * Wv;       // channel-0 row base
    g_pred[idx] = pack_pair(pred, base, xs);
    g_true[idx] = pack_pair(tru,  base, xs);
}

__device__ __forceinline__ float2 bsample(const uint2* __restrict__ P,
                                          float x, float y) {
    // clip to [0, W-1] / [0, H-1] (matches jnp.clip)
    x = fminf(fmaxf(x, 0.0f), (float)(Wv - 1));
    y = fminf(fmaxf(y, 0.0f), (float)(Hv - 1));
    float xf = floorf(x);
    float yf = floorf(y);
    int xi = (int)xf;
    int yi = (int)yf;
    int yi1 = min(yi + 1, Hv - 1);
    __half2 wx2 = __float2half2_rn(x - xf);
    __half2 wy2 = __float2half2_rn(y - yf);

    uint2 r0 = __ldg(P + yi  * WPAD + xi);
    uint2 r1 = __ldg(P + yi1 * WPAD + xi);
    __half2 v00 = *reinterpret_cast<__half2*>(&r0.x);
    __half2 v01 = *reinterpret_cast<__half2*>(&r0.y);
    __half2 v10 = *reinterpret_cast<__half2*>(&r1.x);
    __half2 v11 = *reinterpret_cast<__half2*>(&r1.y);

    __half2 top = __hfma2(wx2, __hsub2(v01, v00), v00);
    __half2 bot = __hfma2(wx2, __hsub2(v11, v10), v10);
    __half2 res = __hfma2(wy2, __hsub2(bot, top), top);
    return __half22float2(res);
}

__global__ __launch_bounds__(256) void traj_kernel() {
    int x = blockIdx.x * blockDim.x + threadIdx.x;  // 0..767
    int y = blockIdx.y;
    int b = blockIdx.z;
    const uint2* __restrict__ Pp = g_pred + b * PK_PLANE;
    const uint2* __restrict__ Pt = g_true + b * PK_PLANE;

    float pxp = (float)x, pyp = (float)y;   // pred trajectory
    float pxt = (float)x, pyt = (float)y;   // true trajectory
    float acc = 0.0f;

    #pragma unroll
    for (int s = 0; s < NSTEPS; s++) {
        float2 vp = bsample(Pp, pxp, pyp);
        float2 vt = bsample(Pt, pxt, pyt);
        pxp = fmaf(DXC, vp.x, pxp);
        pyp = fmaf(DXC, vp.y, pyp);
        pxt = fmaf(DXC, vt.x, pxt);
        pyt = fmaf(DXC, vt.y, pyt);
        float dx = pxt - pxp;
        float dy = pyt - pyp;
        acc = fmaf(dx, dx, acc);
        acc = fmaf(dy, dy, acc);
    }

    // block reduction: warp shuffle -> shared -> warp0 -> atomicAdd(double)
    float v = acc;
    #pragma unroll
    for (int o = 16; o > 0; o >>= 1)
        v += __shfl_down_sync(0xffffffffu, v, o);

    __shared__ float sred[8];
    int lane = threadIdx.x & 31;
    int wid  = threadIdx.x >> 5;
    if (lane == 0) sred[wid] = v;
    __syncthreads();
    if (wid == 0) {
        v = (lane < 8) ? sred[lane] : 0.0f;
        #pragma unroll
        for (int o = 4; o > 0; o >>= 1)
            v += __shfl_down_sync(0xffffffffu, v, o);
        if (lane == 0) atomicAdd(&g_acc, (double)v);
    }
}

__global__ void finalize_kernel(float* __restrict__ out) {
    const double cnt = (double)(NSTEPS + 1) * Bv * 2 * Hv * Wv;  // 84934656
    *out = (float)(g_acc / cnt);
}

extern "C" void kernel_launch(void* const* d_in, const int* in_sizes, int n_in,
                              void* d_out, int out_size) {
    const float* vf_pred = (const float*)d_in[0];
    const float* vf_true = (const float*)d_in[1];
    float* out = (float*)d_out;

    int rp_blocks = (PK_TOTAL + 255) / 256;
    repack_kernel<<<rp_blocks, 256>>>(vf_pred, vf_true);

    dim3 grid(Wv / 256, Hv, Bv);
    traj_kernel<<<grid, 256>>>();

    finalize_kernel<<<1, 1>>>(out);
}